// round 9
// baseline (speedup 1.0000x reference)
#include <cuda_runtime.h>

// Shapes fixed by the dataset: u (B=64, L=8192), ev (K=32, L), lam (K)
#define L      8192
#define NB     64
#define NK     32
#define HALF   4096   // L/2
#define KD     2048   // number of odd d < L/2

// Device scratch (no allocs allowed)
__device__ float g_ct2[KD];   // (2/L)*cot(pi*(2k+1)/L)
__device__ float g_P[L];      // P[l] = sum_k lam_k ev[k][l]
__device__ float g_Po[HALF];  // P at odd l
__device__ float g_Pe[HALF];  // P at even l
__device__ float g_a[NB];     // Re(sum_i rfft(u)[b,i])  (final)
__device__ float g_c[NB];     // Im(sum_i rfft(u)[b,i])  (final)

// ---------------------------------------------------------------------------
// k1: 128 blocks x 1024 threads — single wave.
//  blocks [0,64):   full a/c reduction for batch b = bx (final values).
//  blocks [64,128): P (warp per float4-of-l, lane = k), parity copies, ct2.
__global__ void __launch_bounds__(1024) k1(const float* __restrict__ u,
                                           const float* __restrict__ ev,
                                           const float* __restrict__ lam) {
    const int t  = threadIdx.x;
    const int bx = blockIdx.x;

    if (bx < NB) {
        __shared__ float wa[32], wc[32];
        const int b = bx;
        const float4* u4 = (const float4*)(u + (size_t)b * L);
        float a = 0.0f, c = 0.0f;
#pragma unroll
        for (int r = 0; r < 2; r++) {
            int i = r * 1024 + t;                // float4 index, 2048 per row
            float4 uv = u4[i];
            float x1 = (float)(4 * i + 1) * (1.0f / (float)L);
            float x3 = (float)(4 * i + 3) * (1.0f / (float)L);
            float c1 = __fdividef(cospif(x1), sinpif(x1));
            float c3 = __fdividef(cospif(x3), sinpif(x3));
            a += uv.x + uv.z;
            c -= uv.y * c1 + uv.w * c3;
            if (i == 0) a += (float)(L / 2) * uv.x;
        }
#pragma unroll
        for (int off = 16; off > 0; off >>= 1) {
            a += __shfl_down_sync(0xffffffffu, a, off);
            c += __shfl_down_sync(0xffffffffu, c, off);
        }
        const int lane = t & 31, w = t >> 5;
        if (lane == 0) { wa[w] = a; wc[w] = c; }
        __syncthreads();
        if (t < 32) {
            float av = wa[t], cv = wc[t];
#pragma unroll
            for (int off = 16; off > 0; off >>= 1) {
                av += __shfl_down_sync(0xffffffffu, av, off);
                cv += __shfl_down_sync(0xffffffffu, cv, off);
            }
            if (t == 0) { g_a[b] = av; g_c[b] = cv; }
        }
        return;
    }

    // ---- P blocks ----
    const int pb = bx - NB;             // 0..63
    const int l4 = pb * 32 + (t >> 5);  // float4-of-l index (0..2047)
    const int k  = t & 31;              // eigenvector row
    float4 e  = ((const float4*)ev)[k * (L / 4) + l4];
    float  lk = __ldg(lam + k);
    float4 v; v.x = lk * e.x; v.y = lk * e.y; v.z = lk * e.z; v.w = lk * e.w;
#pragma unroll
    for (int off = 16; off > 0; off >>= 1) {
        v.x += __shfl_down_sync(0xffffffffu, v.x, off);
        v.y += __shfl_down_sync(0xffffffffu, v.y, off);
        v.z += __shfl_down_sync(0xffffffffu, v.z, off);
        v.w += __shfl_down_sync(0xffffffffu, v.w, off);
    }
    if (k == 0) {
        ((float4*)g_P)[l4] = v;
        g_Pe[2 * l4]     = v.x;  g_Po[2 * l4]     = v.y;
        g_Pe[2 * l4 + 1] = v.z;  g_Po[2 * l4 + 1] = v.w;
    }
    if (t < 32) {
        int idx = pb * 32 + t;          // 0..2047
        float x = (float)(2 * idx + 1) * (1.0f / (float)L);
        g_ct2[idx] = (2.0f / (float)L) * __fdividef(cospif(x), sinpif(x));
    }
}

// ---------------------------------------------------------------------------
// k2: 512 blocks x 256 threads, 4 resident blocks/SM — ALL blocks resident
// (512 <= 4*148), so block-serial phases (stage/BAR/reduce) overlap other
// blocks' FMA loops. Block qb: p = qb>>8 (parity), m0 = (qb&255)*16 — 16
// l-values: l = 2*(m0+mm)+p, mm in [0,16).
// Thread (ly = t&3, j = t>>2 in [0,64)): 4m x 32k register tile, 8 chained
// 4x4 subtiles, rolling A/B float4 regs, CT via __ldg. Split accumulators.
__global__ void __launch_bounds__(256, 4) k2(float* __restrict__ out) {
    __shared__ alignas(16) float SA[2080];
    __shared__ alignas(16) float SB[2080];
    __shared__ alignas(16) float red2[8 * 20];
    __shared__ float Ps[16], aS[NB], cS[NB], Qs[16];

    const int t  = threadIdx.x;
    const int qb = blockIdx.x;
    const int p  = qb >> 8;
    const int m0 = (qb & 255) * 16;

    // Stage shifted copies of the opposite-parity half of P:
    //   A(m,k) = S[m+k+p]    -> SA[x] = S[(m0+p+x) & 4095],       A = SA[mm+k]
    //   B(m,k) = S[m-k-1+p]  -> SB[y] = S[(m0+p-2052+y) & 4095],  B = SB[mm-k+2051]
    {
        const float* S = p ? g_Pe : g_Po;
        const int baseA = m0 + p;
        const int baseB = m0 + p - 2052 + HALF;   // keep positive before mask
#pragma unroll
        for (int x = t; x < 2080; x += 256) {
            SA[x] = S[(baseA + x) & (HALF - 1)];
            SB[x] = S[(baseB + x) & (HALF - 1)];
        }
    }
    if (t < NB) {
        aS[t] = g_a[t]; cS[t] = g_c[t];
    } else if (t < NB + 16) {
        Ps[t - NB] = g_P[2 * (m0 + t - NB) + p];
    }
    __syncthreads();

    const int ly = t & 3;               // m-subtile: m = m0 + 4*ly + r
    const int j  = t >> 2;              // 0..63, k-range [32j, 32j+32)
    const float4* SA4 = (const float4*)SA;
    const float4* SB4 = (const float4*)SB;
    const float4* CT4 = (const float4*)g_ct2;

    const int xa0 = ly + 8 * j;         // A float4 base at kt=0
    const int xb0 = 512 + ly - 8 * j;   // B low float4 base at kt=0

    float4 A0 = SA4[xa0];               // a0..a3 for current kt
    float4 B1 = SB4[xb0 + 1];           // b4..b7 for current kt

    float p0 = 0.f, p1 = 0.f, p2 = 0.f, p3 = 0.f;   // + accumulators (C*a)
    float n0 = 0.f, n1 = 0.f, n2 = 0.f, n3 = 0.f;   // - accumulators (C*b)
#pragma unroll
    for (int kt = 0; kt < 8; kt++) {
        float4 A1 = SA4[xa0 + kt + 1];  // a4..a7
        float4 B0 = SB4[xb0 - kt];      // b0..b3
        float4 C  = __ldg(&CT4[8 * j + kt]);
        float a0 = A0.x, a1 = A0.y, a2 = A0.z, a3 = A0.w;
        float a4 = A1.x, a5 = A1.y, a6 = A1.z;
        float b0 = B0.x, b1 = B0.y, b2 = B0.z, b3 = B0.w;
        float b4 = B1.x, b5 = B1.y, b6 = B1.z;
        // accP[r] += C[s]*a[r+s];  accN[r] += C[s]*b[3+r-s]
        p0 = fmaf(C.x, a0, p0); n0 = fmaf(C.x, b3, n0);
        p0 = fmaf(C.y, a1, p0); n0 = fmaf(C.y, b2, n0);
        p0 = fmaf(C.z, a2, p0); n0 = fmaf(C.z, b1, n0);
        p0 = fmaf(C.w, a3, p0); n0 = fmaf(C.w, b0, n0);
        p1 = fmaf(C.x, a1, p1); n1 = fmaf(C.x, b4, n1);
        p1 = fmaf(C.y, a2, p1); n1 = fmaf(C.y, b3, n1);
        p1 = fmaf(C.z, a3, p1); n1 = fmaf(C.z, b2, n1);
        p1 = fmaf(C.w, a4, p1); n1 = fmaf(C.w, b1, n1);
        p2 = fmaf(C.x, a2, p2); n2 = fmaf(C.x, b5, n2);
        p2 = fmaf(C.y, a3, p2); n2 = fmaf(C.y, b4, n2);
        p2 = fmaf(C.z, a4, p2); n2 = fmaf(C.z, b3, n2);
        p2 = fmaf(C.w, a5, p2); n2 = fmaf(C.w, b2, n2);
        p3 = fmaf(C.x, a3, p3); n3 = fmaf(C.x, b6, n3);
        p3 = fmaf(C.y, a4, p3); n3 = fmaf(C.y, b5, n3);
        p3 = fmaf(C.z, a5, p3); n3 = fmaf(C.z, b4, n3);
        p3 = fmaf(C.w, a6, p3); n3 = fmaf(C.w, b3, n3);
        A0 = A1;                        // rolling reuse: A window +1, B window -1
        B1 = B0;
    }
    float acc0 = p0 - n0, acc1 = p1 - n1, acc2 = p2 - n2, acc3 = p3 - n3;

    // Warp reduce over the 8 j's sharing each ly (lane = 4*(j&7) + ly).
    acc0 += __shfl_down_sync(0xffffffffu, acc0, 16);
    acc1 += __shfl_down_sync(0xffffffffu, acc1, 16);
    acc2 += __shfl_down_sync(0xffffffffu, acc2, 16);
    acc3 += __shfl_down_sync(0xffffffffu, acc3, 16);
    acc0 += __shfl_down_sync(0xffffffffu, acc0, 8);
    acc1 += __shfl_down_sync(0xffffffffu, acc1, 8);
    acc2 += __shfl_down_sync(0xffffffffu, acc2, 8);
    acc3 += __shfl_down_sync(0xffffffffu, acc3, 8);
    acc0 += __shfl_down_sync(0xffffffffu, acc0, 4);
    acc1 += __shfl_down_sync(0xffffffffu, acc1, 4);
    acc2 += __shfl_down_sync(0xffffffffu, acc2, 4);
    acc3 += __shfl_down_sync(0xffffffffu, acc3, 4);

    const int lane = t & 31, w = t >> 5;
    if (lane < 4) {
        float4 v; v.x = acc0; v.y = acc1; v.z = acc2; v.w = acc3;
        ((float4*)(red2 + w * 20))[lane] = v;     // red2[w*20 + 4*ly + r]
    }
    __syncthreads();

    if (t < 16) {
        float s = 0.0f;
#pragma unroll
        for (int w2 = 0; w2 < 8; w2++) s += red2[w2 * 20 + t];
        Qs[t] = s;                       // ct2 already carries 2/L
    }
    __syncthreads();

    // 64 b x 16 m outputs, 4 per thread
#pragma unroll
    for (int r = 0; r < 4; r++) {
        int idx = r * 256 + t;
        int b   = idx >> 4;
        int mm  = idx & 15;
        out[(size_t)b * L + 2 * (m0 + mm) + p] =
            fmaf(aS[b], Ps[mm], cS[b] * Qs[mm]);
    }
}

// ---------------------------------------------------------------------------
extern "C" void kernel_launch(void* const* d_in, const int* in_sizes, int n_in,
                              void* d_out, int out_size) {
    const float* u   = (const float*)d_in[0];  // (64, 8192)
    const float* ev  = (const float*)d_in[1];  // (32, 8192)
    const float* lam = (const float*)d_in[2];  // (32,)
    float* out = (float*)d_out;                // (64, 8192)

    k1<<<128, 1024>>>(u, ev, lam);
    k2<<<512, 256>>>(out);
}

// round 10
// speedup vs baseline: 1.1792x; 1.1792x over previous
#include <cuda_runtime.h>

// Shapes fixed by the dataset: u (B=64, L=8192), ev (K=32, L), lam (K)
#define L      8192
#define NB     64
#define NK     32
#define HALF   4096   // L/2
#define KD     2048   // number of odd d < L/2
#define NBLK   128    // grid size (all co-resident: 1 block/SM, 128 <= 148)

// Device scratch (no allocs allowed)
__device__ float g_ct2[KD];   // (2/L)*cot(pi*(2k+1)/L)
__device__ float g_P[L];      // P[l] = sum_k lam_k ev[k][l]
__device__ float g_Po[HALF];  // P at odd l
__device__ float g_Pe[HALF];  // P at even l
__device__ float g_a[NB];     // Re(sum_i rfft(u)[b,i])
__device__ float g_c[NB];     // Im(sum_i rfft(u)[b,i])
__device__ int   g_cnt;       // grid-barrier epoch counter (monotonic across
                              // launches; each launch adds exactly NBLK)

// ---------------------------------------------------------------------------
// Fused persistent kernel: 128 blocks x 1024 threads, all resident.
// Phase 1: blocks [0,64)  -> a_b, c_b for batch b = bx
//          blocks [64,128)-> P (warp per float4-of-l, lane = k), parity
//                            copies, ct2 table
// Grid barrier (atomic counter, round-up-to-multiple-of-128 target -> safe
// across unlimited graph replays).
// Phase 2: block bx: p = bx>>6 (parity), m0 = (bx&63)*64 — 64 l-values
//          l = 2*(m0+mm)+p. Thread (ly = t&15, j = t>>4): 4m x 32k register
//          tile, 8 chained 4x4 subtiles, rolling A/B float4 regs, split
//          accumulators, CT via __ldg. Fused output for all 64 batches.
__global__ void __launch_bounds__(1024) kfused(const float* __restrict__ u,
                                               const float* __restrict__ ev,
                                               const float* __restrict__ lam,
                                               float* __restrict__ out) {
    __shared__ alignas(16) float SA[2112];
    __shared__ alignas(16) float SB[2120];
    __shared__ alignas(16) float red2[32 * 68];
    __shared__ float Ps[64], aS[NB], cS[NB], Qs[64];
    __shared__ float wa[32], wc[32];

    const int t  = threadIdx.x;
    const int bx = blockIdx.x;

    // ======================= Phase 1 =======================
    if (bx < NB) {
        // ---- a/c reduction for batch b = bx ----
        const float4* u4 = (const float4*)(u + (size_t)bx * L);
        float a = 0.0f, c = 0.0f;
#pragma unroll
        for (int r = 0; r < 2; r++) {
            int i = r * 1024 + t;                 // float4 index, 2048 per row
            float4 uv = u4[i];
            float x1 = (float)(4 * i + 1) * (1.0f / (float)L);
            float x3 = (float)(4 * i + 3) * (1.0f / (float)L);
            float c1 = __fdividef(cospif(x1), sinpif(x1));
            float c3 = __fdividef(cospif(x3), sinpif(x3));
            a += uv.x + uv.z;
            c -= uv.y * c1 + uv.w * c3;
            if (i == 0) a += (float)(L / 2) * uv.x;
        }
#pragma unroll
        for (int off = 16; off > 0; off >>= 1) {
            a += __shfl_down_sync(0xffffffffu, a, off);
            c += __shfl_down_sync(0xffffffffu, c, off);
        }
        const int lane = t & 31, w = t >> 5;
        if (lane == 0) { wa[w] = a; wc[w] = c; }
        __syncthreads();
        if (t < 32) {
            float av = wa[t], cv = wc[t];
#pragma unroll
            for (int off = 16; off > 0; off >>= 1) {
                av += __shfl_down_sync(0xffffffffu, av, off);
                cv += __shfl_down_sync(0xffffffffu, cv, off);
            }
            if (t == 0) { g_a[bx] = av; g_c[bx] = cv; }
        }
    } else {
        // ---- P chunk ----
        const int pb = bx - NB;             // 0..63
        const int l4 = pb * 32 + (t >> 5);  // float4-of-l index (0..2047)
        const int k  = t & 31;              // eigenvector row
        float4 e  = ((const float4*)ev)[k * (L / 4) + l4];
        float  lk = __ldg(lam + k);
        float4 v; v.x = lk * e.x; v.y = lk * e.y; v.z = lk * e.z; v.w = lk * e.w;
#pragma unroll
        for (int off = 16; off > 0; off >>= 1) {
            v.x += __shfl_down_sync(0xffffffffu, v.x, off);
            v.y += __shfl_down_sync(0xffffffffu, v.y, off);
            v.z += __shfl_down_sync(0xffffffffu, v.z, off);
            v.w += __shfl_down_sync(0xffffffffu, v.w, off);
        }
        if (k == 0) {
            ((float4*)g_P)[l4] = v;
            g_Pe[2 * l4]     = v.x;  g_Po[2 * l4]     = v.y;
            g_Pe[2 * l4 + 1] = v.z;  g_Po[2 * l4 + 1] = v.w;
        }
        if (t < 32) {
            int idx = pb * 32 + t;          // 0..2047
            float x = (float)(2 * idx + 1) * (1.0f / (float)L);
            g_ct2[idx] = (2.0f / (float)L) * __fdividef(cospif(x), sinpif(x));
        }
        __syncthreads();   // keep phase-1 barrier count identical on all paths
    }

    // ======================= Grid barrier =======================
    __threadfence();                        // publish phase-1 writes (L2)
    if (t == 0) {
        int old = atomicAdd(&g_cnt, 1);
        int target = ((old >> 7) + 1) << 7; // round old+1 up to multiple of 128
        while (*(volatile int*)&g_cnt < target) __nanosleep(64);
    }
    __syncthreads();

    // ======================= Phase 2 =======================
    const int p  = bx >> 6;
    const int m0 = (bx & 63) * 64;

    // Stage shifted copies of the opposite-parity half of P:
    //   A(m,k) = S[m+k+p]    -> SA[x] = S[(m0+p+x) & 4095],       A = SA[mm+k]
    //   B(m,k) = S[m-k-1+p]  -> SB[y] = S[(m0+p-2052+y) & 4095],  B = SB[mm-k+2051]
    {
        const float* S = p ? g_Pe : g_Po;
        const int baseA = m0 + p;
        const int baseB = m0 + p - 2052 + HALF;   // keep positive before mask
#pragma unroll
        for (int x = t; x < 2112; x += 1024) SA[x] = S[(baseA + x) & (HALF - 1)];
#pragma unroll
        for (int y = t; y < 2120; y += 1024) SB[y] = S[(baseB + y) & (HALF - 1)];
    }
    if (t < NB) {
        aS[t] = g_a[t]; cS[t] = g_c[t];
    } else if (t < NB + 64) {
        int mm = t - NB;
        Ps[mm] = g_P[2 * (m0 + mm) + p];
    }
    __syncthreads();

    const int ly = t & 15;              // m-subtile: m = m0 + 4*ly + r
    const int j  = t >> 4;              // 0..63, k-range [32j, 32j+32)
    const float4* SA4 = (const float4*)SA;
    const float4* SB4 = (const float4*)SB;
    const float4* CT4 = (const float4*)g_ct2;

    const int xa0 = ly + 8 * j;         // A float4 base at kt=0
    const int xb0 = 512 + ly - 8 * j;   // B low float4 base at kt=0

    float4 A0 = SA4[xa0];               // a0..a3 for current kt
    float4 B1 = SB4[xb0 + 1];           // b4..b7 for current kt

    float p0 = 0.f, p1 = 0.f, p2 = 0.f, p3 = 0.f;   // + accumulators (C*a)
    float n0 = 0.f, n1 = 0.f, n2 = 0.f, n3 = 0.f;   // - accumulators (C*b)
#pragma unroll
    for (int kt = 0; kt < 8; kt++) {
        float4 A1 = SA4[xa0 + kt + 1];  // a4..a7
        float4 B0 = SB4[xb0 - kt];      // b0..b3
        float4 C  = __ldg(&CT4[8 * j + kt]);
        float a0 = A0.x, a1 = A0.y, a2 = A0.z, a3 = A0.w;
        float a4 = A1.x, a5 = A1.y, a6 = A1.z;
        float b0 = B0.x, b1 = B0.y, b2 = B0.z, b3 = B0.w;
        float b4 = B1.x, b5 = B1.y, b6 = B1.z;
        // accP[r] += C[s]*a[r+s];  accN[r] += C[s]*b[3+r-s]
        p0 = fmaf(C.x, a0, p0); n0 = fmaf(C.x, b3, n0);
        p0 = fmaf(C.y, a1, p0); n0 = fmaf(C.y, b2, n0);
        p0 = fmaf(C.z, a2, p0); n0 = fmaf(C.z, b1, n0);
        p0 = fmaf(C.w, a3, p0); n0 = fmaf(C.w, b0, n0);
        p1 = fmaf(C.x, a1, p1); n1 = fmaf(C.x, b4, n1);
        p1 = fmaf(C.y, a2, p1); n1 = fmaf(C.y, b3, n1);
        p1 = fmaf(C.z, a3, p1); n1 = fmaf(C.z, b2, n1);
        p1 = fmaf(C.w, a4, p1); n1 = fmaf(C.w, b1, n1);
        p2 = fmaf(C.x, a2, p2); n2 = fmaf(C.x, b5, n2);
        p2 = fmaf(C.y, a3, p2); n2 = fmaf(C.y, b4, n2);
        p2 = fmaf(C.z, a4, p2); n2 = fmaf(C.z, b3, n2);
        p2 = fmaf(C.w, a5, p2); n2 = fmaf(C.w, b2, n2);
        p3 = fmaf(C.x, a3, p3); n3 = fmaf(C.x, b6, n3);
        p3 = fmaf(C.y, a4, p3); n3 = fmaf(C.y, b5, n3);
        p3 = fmaf(C.z, a5, p3); n3 = fmaf(C.z, b4, n3);
        p3 = fmaf(C.w, a6, p3); n3 = fmaf(C.w, b3, n3);
        A0 = A1;                        // rolling reuse: A window +1, B window -1
        B1 = B0;
    }
    float acc0 = p0 - n0, acc1 = p1 - n1, acc2 = p2 - n2, acc3 = p3 - n3;

    // Lanes 0-15 of each warp absorb lanes 16-31 (same ly, j+1).
    acc0 += __shfl_down_sync(0xffffffffu, acc0, 16);
    acc1 += __shfl_down_sync(0xffffffffu, acc1, 16);
    acc2 += __shfl_down_sync(0xffffffffu, acc2, 16);
    acc3 += __shfl_down_sync(0xffffffffu, acc3, 16);

    const int lane = t & 31, w = t >> 5;
    if (lane < 16) {
        float4 v; v.x = acc0; v.y = acc1; v.z = acc2; v.w = acc3;
        ((float4*)(red2 + w * 68))[lane] = v;     // red2[w*68 + 4*ly + r]
    }
    __syncthreads();

    if (t < 64) {
        float s = 0.0f;
#pragma unroll
        for (int w2 = 0; w2 < 32; w2++) s += red2[w2 * 68 + t];
        Qs[t] = s;                       // ct2 already carries 2/L
    }
    __syncthreads();

    // 64 b x 64 m outputs, 4 per thread
#pragma unroll
    for (int r = 0; r < 4; r++) {
        int idx = r * 1024 + t;
        int b   = idx >> 6;
        int mm  = idx & 63;
        out[(size_t)b * L + 2 * (m0 + mm) + p] =
            fmaf(aS[b], Ps[mm], cS[b] * Qs[mm]);
    }
}

// ---------------------------------------------------------------------------
extern "C" void kernel_launch(void* const* d_in, const int* in_sizes, int n_in,
                              void* d_out, int out_size) {
    const float* u   = (const float*)d_in[0];  // (64, 8192)
    const float* ev  = (const float*)d_in[1];  // (32, 8192)
    const float* lam = (const float*)d_in[2];  // (32,)
    float* out = (float*)d_out;                // (64, 8192)

    kfused<<<NBLK, 1024>>>(u, ev, lam, out);
}